// round 1
// baseline (speedup 1.0000x reference)
#include <cuda_runtime.h>

// lstm_84567906058356 — the reference's epilogue takes hs[:, -1, :] which is
// BATCH index B-1 (shape (L,B,H) -> (L,H)). Only batch row 8191 contributes
// to the output. So: gather x[:, B-1, 0] (2048 floats), run a scalar
// HIDDEN=3 LSTM recurrence over L=2048 steps on one thread, emit
// out[l] = h_l . w_fc + b_fc.

#define LSTM_LMAX 2048

__device__ __forceinline__ float sigf(float x) {
    // precise enough: EX2-based __expf (few-ulp) + IEEE-ish divide
    return 1.0f / (1.0f + __expf(-x));
}
__device__ __forceinline__ float tanhv(float x) {
    return fmaf(2.0f, sigf(2.0f * x), -1.0f);
}

__global__ void __launch_bounds__(256, 1)
lstm_84567906058356_kernel(const float* __restrict__ x,
                           const float* __restrict__ w_ih,
                           const float* __restrict__ w_hh,
                           const float* __restrict__ b_ih,
                           const float* __restrict__ b_hh,
                           const float* __restrict__ w_fc,
                           const float* __restrict__ b_fc,
                           float* __restrict__ out,
                           int L, int B)
{
    __shared__ float xs[LSTM_LMAX];

    // Parallel gather of the single live batch row: x[l*B + (B-1)].
    int tid = threadIdx.x;
    for (int l = tid; l < L; l += blockDim.x)
        xs[l] = x[(size_t)l * (size_t)B + (size_t)(B - 1)];
    __syncthreads();

    if (tid != 0) return;

    // Load the tiny weights into registers.
    float wih[12], a[12], w0[12], w1[12], w2[12];
#pragma unroll
    for (int g = 0; g < 12; g++) {
        wih[g] = w_ih[g];
        a[g]   = b_ih[g] + b_hh[g];
        w0[g]  = w_hh[g * 3 + 0];
        w1[g]  = w_hh[g * 3 + 1];
        w2[g]  = w_hh[g * 3 + 2];
    }
    const float wf0 = w_fc[0], wf1 = w_fc[1], wf2 = w_fc[2], bfc = b_fc[0];

    float h0 = 0.f, h1 = 0.f, h2 = 0.f;
    float c0 = 0.f, c1 = 0.f, c2 = 0.f;

    for (int l = 0; l < L; l++) {
        const float xt = xs[l];
        float gates[12];
#pragma unroll
        for (int g = 0; g < 12; g++) {
            // x-part first: off the h critical path (compiler hoists it).
            float v = fmaf(xt, wih[g], a[g]);
            v = fmaf(h0, w0[g], v);
            v = fmaf(h1, w1[g], v);
            v = fmaf(h2, w2[g], v);
            gates[g] = v;
        }
        // split order: i = [0:3), f = [3:6), g = [6:9), o = [9:12)
        const float i0 = sigf(gates[0]),  i1 = sigf(gates[1]),  i2 = sigf(gates[2]);
        const float f0 = sigf(gates[3]),  f1 = sigf(gates[4]),  f2 = sigf(gates[5]);
        const float g0 = tanhv(gates[6]), g1 = tanhv(gates[7]), g2 = tanhv(gates[8]);
        const float o0 = sigf(gates[9]),  o1 = sigf(gates[10]), o2 = sigf(gates[11]);

        c0 = fmaf(f0, c0, i0 * g0);
        c1 = fmaf(f1, c1, i1 * g1);
        c2 = fmaf(f2, c2, i2 * g2);

        h0 = o0 * tanhv(c0);
        h1 = o1 * tanhv(c1);
        h2 = o2 * tanhv(c2);

        // out[l] = h . w_fc + b_fc  (store is fire-and-forget, off-chain)
        out[l] = fmaf(h0, wf0, fmaf(h1, wf1, fmaf(h2, wf2, bfc)));
    }
}

extern "C" void kernel_launch(void* const* d_in, const int* in_sizes, int n_in,
                              void* d_out, int out_size)
{
    const float* x    = (const float*)d_in[0];
    const float* w_ih = (const float*)d_in[1];
    const float* w_hh = (const float*)d_in[2];
    const float* b_ih = (const float*)d_in[3];
    const float* b_hh = (const float*)d_in[4];
    const float* w_fc = (const float*)d_in[5];
    const float* b_fc = (const float*)d_in[6];

    const int L = out_size;              // 2048 (one output scalar per timestep)
    const int B = in_sizes[0] / L;       // 8192

    lstm_84567906058356_kernel<<<1, 256>>>(x, w_ih, w_hh, b_ih, b_hh,
                                           w_fc, b_fc, (float*)d_out, L, B);
}

// round 2
// speedup vs baseline: 14.3617x; 14.3617x over previous
#include <cuda_runtime.h>

// lstm_84567906058356 — only batch row B-1 contributes (reference takes
// hs[:, -1, :] on a (L,B,H) tensor = batch index, not time). HIDDEN=3.
// R2: MUFU.TANH activations + 3-lane warp-parallel recurrence.
//   lane k (k=0..2) owns hidden unit k and computes its own i/f/g/o gates;
//   sigmoid(v) = 0.5 + 0.5*tanh(v/2) with the 0.5 pre-folded into weights.
//   Only cross-lane traffic: one h-broadcast (3 shfl) per step.

#define LSTM_LMAX 2048

__device__ __forceinline__ float tanh_ap(float x) {
    float y;
    asm("tanh.approx.f32 %0, %1;" : "=f"(y) : "f"(x));
    return y;
}

__global__ void __launch_bounds__(256, 1)
lstm_84567906058356_kernel(const float* __restrict__ x,
                           const float* __restrict__ w_ih,
                           const float* __restrict__ w_hh,
                           const float* __restrict__ b_ih,
                           const float* __restrict__ b_hh,
                           const float* __restrict__ w_fc,
                           const float* __restrict__ b_fc,
                           float* __restrict__ out,
                           int L, int B)
{
    __shared__ float xs[LSTM_LMAX];

    // Parallel gather of the single live batch row: x[l*B + (B-1)].
    const int tid = threadIdx.x;
    for (int l = tid; l < L; l += blockDim.x)
        xs[l] = x[(size_t)l * (size_t)B + (size_t)(B - 1)];
    __syncthreads();

    if (tid >= 32) return;          // recurrence runs on warp 0 only

    const int lane = tid;
    const int k = lane < 3 ? lane : 2;   // lanes 3..31 shadow lane 2 (warp-uniform flow)

    // Gate rows (after jnp.split order): i = k, f = 3+k, g = 6+k, o = 9+k.
    // Sigmoid gates (i,f,o) get all coefficients pre-scaled by 0.5.
    const int ri = k, rf = 3 + k, rg = 6 + k, ro = 9 + k;

    const float wi0 = 0.5f * w_hh[ri*3+0], wi1 = 0.5f * w_hh[ri*3+1], wi2 = 0.5f * w_hh[ri*3+2];
    const float wf0 = 0.5f * w_hh[rf*3+0], wf1 = 0.5f * w_hh[rf*3+1], wf2 = 0.5f * w_hh[rf*3+2];
    const float wg0 =        w_hh[rg*3+0], wg1 =        w_hh[rg*3+1], wg2 =        w_hh[rg*3+2];
    const float wo0 = 0.5f * w_hh[ro*3+0], wo1 = 0.5f * w_hh[ro*3+1], wo2 = 0.5f * w_hh[ro*3+2];

    const float wihi = 0.5f * w_ih[ri], ai = 0.5f * (b_ih[ri] + b_hh[ri]);
    const float wihf = 0.5f * w_ih[rf], af = 0.5f * (b_ih[rf] + b_hh[rf]);
    const float wihg =        w_ih[rg], ag =         b_ih[rg] + b_hh[rg];
    const float wiho = 0.5f * w_ih[ro], ao = 0.5f * (b_ih[ro] + b_hh[ro]);

    const float wfc0 = w_fc[0], wfc1 = w_fc[1], wfc2 = w_fc[2], bfc = b_fc[0];

    float h0 = 0.f, h1 = 0.f, h2 = 0.f;
    float halfc = 0.f;                   // 0.5 * c_k (lane-private)

    // Prime the x-contributions for step 0.
    float xt  = xs[0];
    float xpi = fmaf(xt, wihi, ai);
    float xpf = fmaf(xt, wihf, af);
    float xpg = fmaf(xt, wihg, ag);
    float xpo = fmaf(xt, wiho, ao);

    for (int l = 0; l < L; l++) {
        // Gate pre-activations (4 independent 3-FMA chains).
        float vg = fmaf(h0, wg0, xpg); vg = fmaf(h1, wg1, vg); vg = fmaf(h2, wg2, vg);
        float vi = fmaf(h0, wi0, xpi); vi = fmaf(h1, wi1, vi); vi = fmaf(h2, wi2, vi);
        float vf = fmaf(h0, wf0, xpf); vf = fmaf(h1, wf1, vf); vf = fmaf(h2, wf2, vf);
        float vo = fmaf(h0, wo0, xpo); vo = fmaf(h1, wo1, vo); vo = fmaf(h2, wo2, vo);

        float tg = tanh_ap(vg);          // tanh(g)
        float ti = tanh_ap(vi);          // sigmoid(i) = 0.5 + 0.5*ti
        float tf = tanh_ap(vf);
        float to = tanh_ap(vo);

        // Prefetch next x while MUFUs are in flight (off critical path).
        const int ln = (l + 1 < L) ? l + 1 : l;
        const float xt2 = xs[ln];

        // c' = f*c + i*g  with folds:
        //   i*g = (0.5+0.5ti)*tg = u + ti*u,  u = 0.5*tg
        //   f*c = (0.5+0.5tf)*c  = halfc + tf*halfc
        const float u  = 0.5f * tg;
        const float ig = fmaf(ti, u, u);
        const float r  = halfc + ig;
        const float c2 = fmaf(tf, halfc, r);

        const float tc   = tanh_ap(c2);
        const float top1 = fmaf(0.5f, to, 0.5f);   // = sigmoid(o)... times 1: h = top1*tc
        const float h    = tc * top1;
        halfc = 0.5f * c2;

        h0 = __shfl_sync(0xffffffffu, h, 0);
        h1 = __shfl_sync(0xffffffffu, h, 1);
        h2 = __shfl_sync(0xffffffffu, h, 2);

        // Output projection (off critical path; lane 0 stores).
        float ov = fmaf(h2, wfc2, bfc);
        ov = fmaf(h1, wfc1, ov);
        ov = fmaf(h0, wfc0, ov);
        if (lane == 0) out[l] = ov;

        // Next step's x contributions (independent of the h chain).
        xpi = fmaf(xt2, wihi, ai);
        xpf = fmaf(xt2, wihf, af);
        xpg = fmaf(xt2, wihg, ag);
        xpo = fmaf(xt2, wiho, ao);
    }
}

extern "C" void kernel_launch(void* const* d_in, const int* in_sizes, int n_in,
                              void* d_out, int out_size)
{
    const float* x    = (const float*)d_in[0];
    const float* w_ih = (const float*)d_in[1];
    const float* w_hh = (const float*)d_in[2];
    const float* b_ih = (const float*)d_in[3];
    const float* b_hh = (const float*)d_in[4];
    const float* w_fc = (const float*)d_in[5];
    const float* b_fc = (const float*)d_in[6];

    const int L = out_size;              // 2048
    const int B = in_sizes[0] / L;       // 8192

    lstm_84567906058356_kernel<<<1, 256>>>(x, w_ih, w_hh, b_ih, b_hh,
                                           w_fc, b_fc, (float*)d_out, L, B);
}

// round 4
// speedup vs baseline: 15.3751x; 1.0706x over previous
#include <cuda_runtime.h>

// lstm_84567906058356 — only batch row B-1 contributes (reference takes
// hs[:, -1, :] of a (L,B,H) tensor = batch index B-1, not last timestep).
// HIDDEN=3, L=2048. Scalar recurrence on warp 0, 3 live lanes.
//
// R4: - 2 shuffles/step total; previous step's output projection reuses the
//       top-of-loop shuffles (deferred store, epilogue handles step L-1)
//     - own-h gate FMAs execute during shfl flight
//     - sigmoid via MUFU.TANH with 0.5 pre-folded into weights/biases
//     - tightened c-fold, tanh issue order g,i,f,o, unroll 4, padded xs

#define LSTM_LMAX 2048

__device__ __forceinline__ float tanh_ap(float x) {
    float y;
    asm("tanh.approx.f32 %0, %1;" : "=f"(y) : "f"(x));
    return y;
}

__global__ void __launch_bounds__(256, 1)
lstm_84567906058356_kernel(const float* __restrict__ x,
                           const float* __restrict__ w_ih,
                           const float* __restrict__ w_hh,
                           const float* __restrict__ b_ih,
                           const float* __restrict__ b_hh,
                           const float* __restrict__ w_fc,
                           const float* __restrict__ b_fc,
                           float* __restrict__ out,
                           int L, int B)
{
    __shared__ float xs[LSTM_LMAX + 8];

    // Parallel gather of the single live batch row: x[l*B + (B-1)].
    const int tid = threadIdx.x;
    for (int l = tid; l < L; l += blockDim.x)
        xs[l] = x[(size_t)l * (size_t)B + (size_t)(B - 1)];
    if (tid < 8) xs[LSTM_LMAX + tid] = 0.0f;     // pad: clamp-free prefetch
    __syncthreads();

    if (tid >= 32) return;               // recurrence runs on warp 0 only

    const int lane = tid;
    const int k  = lane < 3 ? lane : 2;  // lanes 3..31 shadow lane 2
    const int rA = (k + 1) % 3;          // remote hidden indices
    const int rB = (k + 2) % 3;

    // Gate rows (jnp.split order): i=k, f=3+k, g=6+k, o=9+k.
    // Sigmoid gates (i,f,o): coefficients pre-scaled by 0.5 so that
    // sigmoid(v) = 0.5 + 0.5*tanh(v_half).
    const int ri = k, rf = 3 + k, rg = 6 + k, ro = 9 + k;

    const float wiO = 0.5f * w_hh[ri*3+k], wiA = 0.5f * w_hh[ri*3+rA], wiB = 0.5f * w_hh[ri*3+rB];
    const float wfO = 0.5f * w_hh[rf*3+k], wfA = 0.5f * w_hh[rf*3+rA], wfB = 0.5f * w_hh[rf*3+rB];
    const float wgO =        w_hh[rg*3+k], wgA =        w_hh[rg*3+rA], wgB =        w_hh[rg*3+rB];
    const float woO = 0.5f * w_hh[ro*3+k], woA = 0.5f * w_hh[ro*3+rA], woB = 0.5f * w_hh[ro*3+rB];

    const float wihi = 0.5f * w_ih[ri], ai = 0.5f * (b_ih[ri] + b_hh[ri]);
    const float wihf = 0.5f * w_ih[rf], af = 0.5f * (b_ih[rf] + b_hh[rf]);
    const float wihg =        w_ih[rg], ag =         b_ih[rg] + b_hh[rg];
    const float wiho = 0.5f * w_ih[ro], ao = 0.5f * (b_ih[ro] + b_hh[ro]);

    const float wfcO = w_fc[k], wfcA = w_fc[rA], wfcB = w_fc[rB], bfc = b_fc[0];

    float h     = 0.f;                   // lane-private h_k
    float halfc = 0.f;                   // 0.5 * c_k

    // Prime step-0 x contributions.
    float xt  = xs[0];
    float xpi = fmaf(xt, wihi, ai);
    float xpf = fmaf(xt, wihf, af);
    float xpg = fmaf(xt, wihg, ag);
    float xpo = fmaf(xt, wiho, ao);

#pragma unroll 4
    for (int l = 0; l < L; l++) {
        // Mandatory shuffles. At this point h/hA/hB are h_{l-1}[k/rA/rB].
        const float hA = __shfl_sync(0xffffffffu, h, rA);
        const float hB = __shfl_sync(0xffffffffu, h, rB);

        // Own-h gate terms execute during shfl flight.
        float vg = fmaf(h, wgO, xpg);
        float vi = fmaf(h, wiO, xpi);
        float vf = fmaf(h, wfO, xpf);
        float vo = fmaf(h, woO, xpo);

        vg = fmaf(hB, wgB, fmaf(hA, wgA, vg));
        vi = fmaf(hB, wiB, fmaf(hA, wiA, vi));
        vf = fmaf(hB, wfB, fmaf(hA, wfA, vf));
        vo = fmaf(hB, woB, fmaf(hA, woA, vo));

        // tanh issue order: earliest-needed first.
        const float tg = tanh_ap(vg);
        const float ti = tanh_ap(vi);
        const float tf = tanh_ap(vf);
        const float to = tanh_ap(vo);

        // --- Off-critical-path work in the MUFU shadow ---
        // (1) deferred projection: out[l-1] uses h_{l-1}, exactly the values
        //     just shuffled. Step 0's "store" targets out[-1] -> predicated off.
        {
            float ov = fmaf(hB, wfcB, bfc);
            ov = fmaf(hA, wfcA, ov);
            ov = fmaf(h,  wfcO, ov);
            if ((lane == 0) & (l > 0)) out[l - 1] = ov;
        }
        // (2) next x (clamp-free thanks to padding).
        const float xt2 = xs[l + 1];

        // c' = sig(f)*c + sig(i)*tanh(g)
        //    = halfc + tf*halfc + 0.5*(tg + ti*tg)
        const float s  = fmaf(ti, tg, tg);
        const float q  = fmaf(0.5f, s, halfc);
        const float c2 = fmaf(tf, halfc, q);

        const float tc   = tanh_ap(c2);
        const float top1 = fmaf(0.5f, to, 0.5f);   // sigmoid(o)
        halfc = 0.5f * c2;
        h = tc * top1;

        // Next step's x contributions (independent of the h chain).
        xpi = fmaf(xt2, wihi, ai);
        xpf = fmaf(xt2, wihf, af);
        xpg = fmaf(xt2, wihg, ag);
        xpo = fmaf(xt2, wiho, ao);
    }

    // Epilogue: projection for the final step (h == h_{L-1}).
    {
        const float hA = __shfl_sync(0xffffffffu, h, rA);
        const float hB = __shfl_sync(0xffffffffu, h, rB);
        float ov = fmaf(hB, wfcB, bfc);
        ov = fmaf(hA, wfcA, ov);
        ov = fmaf(h,  wfcO, ov);
        if (lane == 0) out[L - 1] = ov;
    }
}

extern "C" void kernel_launch(void* const* d_in, const int* in_sizes, int n_in,
                              void* d_out, int out_size)
{
    const float* x    = (const float*)d_in[0];
    const float* w_ih = (const float*)d_in[1];
    const float* w_hh = (const float*)d_in[2];
    const float* b_ih = (const float*)d_in[3];
    const float* b_hh = (const float*)d_in[4];
    const float* w_fc = (const float*)d_in[5];
    const float* b_fc = (const float*)d_in[6];

    const int L = out_size;              // 2048
    const int B = in_sizes[0] / L;       // 8192

    lstm_84567906058356_kernel<<<1, 256>>>(x, w_ih, w_hh, b_ih, b_hh,
                                           w_fc, b_fc, (float*)d_out, L, B);
}